// round 16
// baseline (speedup 1.0000x reference)
#include <cuda_runtime.h>
#include <cuda_fp16.h>
#include <math.h>

#define Bn    2
#define Sn    2048
#define Dn    1024
#define Hn    16
#define HEADn 64
#define RANKn 204
#define RANKP 224
#define BHn   (Bn*Hn)
#define Mn    (Bn*Sn)
#define WSLOT 262144                   // padded weight slot (256*1024 halves)

// ---------------- scratch ----------------
__device__ __half g_xh[3][(size_t)Mn*Dn];
__device__ __half g_tmp[3][(size_t)Mn*RANKP];
__device__ float  g_split[4][(size_t)Mn*RANKP];
__device__ __half g_qp[(size_t)Mn*Dn];
__device__ __half g_kp[(size_t)Mn*Dn];
__device__ __half g_vp[(size_t)Mn*Dn];
__device__ __half g_oh[(size_t)Mn*Dn];
__device__ __half g_wh[8][WSLOT];

// ---------------- helpers ----------------
__device__ __forceinline__ void mma_f16(float4& d, unsigned a0, unsigned a1,
                                        unsigned a2, unsigned a3,
                                        unsigned b0, unsigned b1) {
    asm volatile(
        "mma.sync.aligned.m16n8k16.row.col.f32.f16.f16.f32 "
        "{%0,%1,%2,%3},{%4,%5,%6,%7},{%8,%9},{%0,%1,%2,%3};"
        : "+f"(d.x), "+f"(d.y), "+f"(d.z), "+f"(d.w)
        : "r"(a0), "r"(a1), "r"(a2), "r"(a3), "r"(b0), "r"(b1));
}

__device__ __forceinline__ void ldsm_x4(unsigned& r0, unsigned& r1, unsigned& r2,
                                        unsigned& r3, const __half* p) {
    unsigned addr = (unsigned)__cvta_generic_to_shared(p);
    asm volatile("ldmatrix.sync.aligned.m8n8.x4.shared.b16 {%0,%1,%2,%3}, [%4];"
                 : "=r"(r0), "=r"(r1), "=r"(r2), "=r"(r3) : "r"(addr));
}
__device__ __forceinline__ void ldsm_x2(unsigned& r0, unsigned& r1, const __half* p) {
    unsigned addr = (unsigned)__cvta_generic_to_shared(p);
    asm volatile("ldmatrix.sync.aligned.m8n8.x2.shared.b16 {%0,%1}, [%2];"
                 : "=r"(r0), "=r"(r1) : "r"(addr));
}
__device__ __forceinline__ void ldsm_x2t(unsigned& r0, unsigned& r1, const __half* p) {
    unsigned addr = (unsigned)__cvta_generic_to_shared(p);
    asm volatile("ldmatrix.sync.aligned.m8n8.x2.trans.shared.b16 {%0,%1}, [%2];"
                 : "=r"(r0), "=r"(r1) : "r"(addr));
}

__device__ __forceinline__ uint2 pack4(float4 v) {
    __half2 h0 = __floats2half2_rn(v.x, v.y);
    __half2 h1 = __floats2half2_rn(v.z, v.w);
    return make_uint2(reinterpret_cast<unsigned&>(h0), reinterpret_cast<unsigned&>(h1));
}

__device__ __forceinline__ __half2 ex2h2(__half2 x) {
    __half2 r;
    asm("ex2.approx.f16x2 %0, %1;"
        : "=r"(reinterpret_cast<unsigned&>(r)) : "r"(reinterpret_cast<unsigned&>(x)));
    return r;
}
__device__ __forceinline__ unsigned h2bits(__half2 x) {
    return reinterpret_cast<unsigned&>(x);
}

__device__ __forceinline__ void cpasync16(__half* dst, const __half* src) {
    unsigned d = (unsigned)__cvta_generic_to_shared(dst);
    asm volatile("cp.async.cg.shared.global [%0], [%1], 16;" :: "r"(d), "l"(src) : "memory");
}
#define CP_COMMIT() asm volatile("cp.async.commit_group;" ::: "memory")
#define CP_WAIT0()  asm volatile("cp.async.wait_group 0;"  ::: "memory")
#define CP_WAIT1()  asm volatile("cp.async.wait_group 1;"  ::: "memory")

#define EXSC 0.18033688011112042f   // 0.125 * log2(e)

// ============ merged conversions: q/k/v fp32->fp16 + padded fp16 weights ============
// grid.y: 0-2 -> q/k/v, 3-10 -> weight slot (y-3)
struct WPtrs { const float* src[8]; };

__global__ __launch_bounds__(256) void cvt_all(const float* q, const float* k,
                                               const float* v, __half* xdst,
                                               WPtrs w, __half* wdst) {
    int y = blockIdx.y;
    if (y < 3) {
        const float* s = (y == 0) ? q : (y == 1) ? k : v;
        size_t o = ((size_t)blockIdx.x * 256 + threadIdx.x) * 4;
        float4 t = *(const float4*)&s[o];
        *(uint2*)&xdst[(size_t)y * Mn * Dn + o] = pack4(t);
    } else {
        if (blockIdx.x >= WSLOT / 4 / 256) return;
        int m = y - 3;
        bool isV = (m < 3) || (m == 6);
        size_t o = ((size_t)blockIdx.x * 256 + threadIdx.x) * 4;
        __half* d = wdst + (size_t)m * WSLOT;
        float4 t = make_float4(0.f, 0.f, 0.f, 0.f);
        if (isV) {
            int r = (int)(o >> 10), c = (int)(o & 1023);
            if (r < RANKn) t = *(const float4*)&w.src[m][r * 1024 + c];
        } else {
            if (o >= (size_t)1024 * RANKP) return;
            int r = (int)(o / RANKP), c = (int)(o % RANKP);
            if (c < RANKn) t = *(const float4*)&w.src[m][r * RANKn + c];
        }
        *(uint2*)&d[o] = pack4(t);
    }
}

// ============ gemm_h: pure fp16 NT GEMM, 3-stage cp.async, guard-free ============
struct GemmH {
    const __half* A[3];
    const __half* B[3];
    const float*  bias[3];
    void*         C[3];
};

#define GPH 40

__global__ __launch_bounds__(128) void gemm_h(GemmH gb, int Nreal, int Npitch,
                                              int Klen, int apitch, int bpitch,
                                              int hasBias, int outHalf,
                                              int ksplit, size_t cstride) {
    int z = blockIdx.z;
    int batch = z / ksplit, slice = z % ksplit;
    const __half* A = gb.A[batch] + slice * Klen;
    const __half* B = gb.B[batch] + slice * Klen;
    const float* bias = gb.bias[batch];
    float*  Cf = (float*)gb.C[batch] + (size_t)slice * cstride;
    __half* Ch = (__half*)gb.C[batch];

    __shared__ __half As[3][64 * GPH], Bs[3][64 * GPH];

    int t = threadIdx.x;
    int warp = t >> 5, lane = t & 31;
    int g = lane >> 2, tg = lane & 3;
    int bm = blockIdx.y * 64, bn = blockIdx.x * 64;
    int mbase = (warp & 1) * 32, nbase = (warp >> 1) * 32;

    int a_r = lane & 15, a_c = (lane >> 4) << 3;
    int b_r = lane & 7,  b_c = ((lane >> 3) & 1) << 3;

    int crow[2], cc8[2];
    #pragma unroll
    for (int i = 0; i < 2; i++) { int s = t + i * 128; crow[i] = s >> 2; cc8[i] = (s & 3) * 8; }

    auto issue = [&](int k0, int st) {
        #pragma unroll
        for (int i = 0; i < 2; i++) {
            cpasync16(&As[st][crow[i] * GPH + cc8[i]],
                      &A[(size_t)(bm + crow[i]) * apitch + k0 + cc8[i]]);
            cpasync16(&Bs[st][crow[i] * GPH + cc8[i]],
                      &B[(size_t)(bn + crow[i]) * bpitch + k0 + cc8[i]]);
        }
    };

    float4 acc[2][4];
    #pragma unroll
    for (int i = 0; i < 2; i++)
        #pragma unroll
        for (int j = 0; j < 4; j++) acc[i][j] = make_float4(0.f, 0.f, 0.f, 0.f);

    int nkt = Klen / 32;   // always >= 2 for our shapes
    issue(0, 0);
    CP_COMMIT();
    issue(32, 1);
    CP_COMMIT();

    for (int kt = 0; kt < nkt; kt++) {
        int cur = kt % 3;
        if (kt + 1 < nkt) { CP_WAIT1(); } else { CP_WAIT0(); }
        __syncthreads();
        if (kt + 2 < nkt) { issue((kt + 2) * 32, (kt + 2) % 3); CP_COMMIT(); }

        #pragma unroll
        for (int ko = 0; ko < 32; ko += 16) {
            unsigned a0[4], a1[4];
            ldsm_x4(a0[0], a0[1], a0[2], a0[3], &As[cur][(mbase + a_r) * GPH + ko + a_c]);
            ldsm_x4(a1[0], a1[1], a1[2], a1[3], &As[cur][(mbase + 16 + a_r) * GPH + ko + a_c]);
            #pragma unroll
            for (int ns = 0; ns < 4; ns++) {
                unsigned b0, b1;
                ldsm_x2(b0, b1, &Bs[cur][(nbase + ns * 8 + b_r) * GPH + ko + b_c]);
                mma_f16(acc[0][ns], a0[0], a0[1], a0[2], a0[3], b0, b1);
                mma_f16(acc[1][ns], a1[0], a1[1], a1[2], a1[3], b0, b1);
            }
        }
    }

    #pragma unroll
    for (int ms = 0; ms < 2; ms++) {
        #pragma unroll
        for (int ns = 0; ns < 4; ns++) {
            int col = bn + nbase + ns * 8 + 2 * tg;
            if (col < Npitch) {
                bool real = (col < Nreal);
                float b0 = (hasBias && real) ? bias[col]     : 0.f;
                float b1 = (hasBias && real) ? bias[col + 1] : 0.f;
                int r0 = bm + mbase + ms * 16 + g;
                float vx = real ? acc[ms][ns].x + b0 : 0.f;
                float vy = real ? acc[ms][ns].y + b1 : 0.f;
                float vz = real ? acc[ms][ns].z + b0 : 0.f;
                float vw = real ? acc[ms][ns].w + b1 : 0.f;
                if (outHalf) {
                    *(__half2*)&Ch[(size_t)r0 * Npitch + col]       = __floats2half2_rn(vx, vy);
                    *(__half2*)&Ch[(size_t)(r0 + 8) * Npitch + col] = __floats2half2_rn(vz, vw);
                } else {
                    *(float2*)&Cf[(size_t)r0 * Npitch + col]       = make_float2(vx, vy);
                    *(float2*)&Cf[(size_t)(r0 + 8) * Npitch + col] = make_float2(vz, vw);
                }
            }
        }
    }
}

// ============ gemm_s: sums 4 fp32 partial A buffers, fp16 B, fp32 out ============
__global__ __launch_bounds__(128) void gemm_s(const float* __restrict__ A, size_t astride,
                                              const __half* __restrict__ Bp,
                                              const float* __restrict__ bias,
                                              float* __restrict__ C, int N, int K) {
    __shared__ __half As[2][64 * GPH], Bs[2][64 * GPH];

    int t = threadIdx.x;
    int warp = t >> 5, lane = t & 31;
    int g = lane >> 2, tg = lane & 3;
    int bm = blockIdx.y * 64, bn = blockIdx.x * 64;
    int mbase = (warp & 1) * 32, nbase = (warp >> 1) * 32;

    int a_r = lane & 15, a_c = (lane >> 4) << 3;
    int b_r = lane & 7,  b_c = ((lane >> 3) & 1) << 3;

    int lrow[4], lsc[4];
    #pragma unroll
    for (int i = 0; i < 4; i++) { int idx = t + i * 128; lrow[i] = idx >> 3; lsc[i] = idx & 7; }

    float4 ra[4];
    uint2  rbh[4];
    auto fetch = [&](int k0) {
        #pragma unroll
        for (int i = 0; i < 4; i++) {
            int kk = k0 + lsc[i] * 4;
            size_t aoff = (size_t)(bm + lrow[i]) * K + kk;
            ra[i] = make_float4(0.f, 0.f, 0.f, 0.f);
            #pragma unroll
            for (int p = 0; p < 4; p++) {
                float4 v = *(const float4*)&A[p * astride + aoff];
                ra[i].x += v.x; ra[i].y += v.y; ra[i].z += v.z; ra[i].w += v.w;
            }
            rbh[i] = *(const uint2*)&Bp[(size_t)(bn + lrow[i]) * K + kk];
        }
    };
    auto stage = [&](int s) {
        #pragma unroll
        for (int i = 0; i < 4; i++) {
            *(uint2*)&As[s][lrow[i] * GPH + lsc[i] * 4] = pack4(ra[i]);
            *(uint2*)&Bs[s][lrow[i] * GPH + lsc[i] * 4] = rbh[i];
        }
    };

    float4 acc[2][4];
    #pragma unroll
    for (int i = 0; i < 2; i++)
        #pragma unroll
        for (int j = 0; j < 4; j++) acc[i][j] = make_float4(0.f, 0.f, 0.f, 0.f);

    int nkt = K / 32;
    fetch(0);
    stage(0);
    __syncthreads();

    for (int kt = 0; kt < nkt; kt++) {
        int cur = kt & 1;
        if (kt + 1 < nkt) fetch((kt + 1) * 32);

        #pragma unroll
        for (int ko = 0; ko < 32; ko += 16) {
            unsigned a0[4], a1[4];
            ldsm_x4(a0[0], a0[1], a0[2], a0[3], &As[cur][(mbase + a_r) * GPH + ko + a_c]);
            ldsm_x4(a1[0], a1[1], a1[2], a1[3], &As[cur][(mbase + 16 + a_r) * GPH + ko + a_c]);
            #pragma unroll
            for (int ns = 0; ns < 4; ns++) {
                unsigned b0, b1;
                ldsm_x2(b0, b1, &Bs[cur][(nbase + ns * 8 + b_r) * GPH + ko + b_c]);
                mma_f16(acc[0][ns], a0[0], a0[1], a0[2], a0[3], b0, b1);
                mma_f16(acc[1][ns], a1[0], a1[1], a1[2], a1[3], b0, b1);
            }
        }

        if (kt + 1 < nkt) {
            stage(cur ^ 1);
            __syncthreads();
        }
    }

    #pragma unroll
    for (int ms = 0; ms < 2; ms++) {
        #pragma unroll
        for (int ns = 0; ns < 4; ns++) {
            int col = bn + nbase + ns * 8 + 2 * tg;
            float b0 = bias[col], b1 = bias[col + 1];
            int r0 = bm + mbase + ms * 16 + g;
            *(float2*)&C[(size_t)r0 * N + col]       = make_float2(acc[ms][ns].x + b0, acc[ms][ns].y + b1);
            *(float2*)&C[(size_t)(r0 + 8) * N + col] = make_float2(acc[ms][ns].z + b0, acc[ms][ns].w + b1);
        }
    }
}

// ============ fused causal attention (round-14, unchanged) ============
#define APH 72
#define HTILE (64*APH)
#define HOFF_K HTILE
#define HOFF_V (3*HTILE)
#define SM_H   (5*HTILE)
#define OFF_LP (SM_H*2)
#define OFF_LI (OFF_LP + 512)
#define ATTN_SMEM (OFF_LI + 256)

__global__ __launch_bounds__(128, 4) void attn_fused(const __half* __restrict__ Qp,
                                                     const __half* __restrict__ Kp,
                                                     const __half* __restrict__ Vp,
                                                     float* __restrict__ attn,
                                                     __half* __restrict__ Oh) {
    extern __shared__ char smraw[];
    __half* Qs = (__half*)smraw;
    __half* Kbb = (__half*)smraw + HOFF_K;
    __half* Vbb = (__half*)smraw + HOFF_V;
    float* red   = (float*)(smraw + 3 * HTILE * 2);
    float* lpart = (float*)(smraw + OFF_LP);
    float* linv  = (float*)(smraw + OFF_LI);

    int qt = gridDim.x - 1 - blockIdx.x;
    int bh = blockIdx.y;
    int b = bh >> 4, h = bh & 15;
    int q0 = qt * 64;

    int t = threadIdx.x;
    int warp = t >> 5, lane = t & 31;
    int g = lane >> 2, tg = lane & 3;
    int wm = warp & 1, wn = warp >> 1;
    int mbase = wm * 32, nbase = wn * 32;

    int a_r = lane & 15, a_c = (lane >> 4) << 3;
    int bq_r = lane & 7, bq_c = ((lane >> 3) & 1) << 3;
    int bv_r = lane & 15;

    int frow[4], fc8[4];
    #pragma unroll
    for (int i = 0; i < 4; i++) { int s = t + i * 128; frow[i] = s >> 3; fc8[i] = (s & 7) * 8; }

    const __half* Kbase = Kp + (size_t)(b * Sn) * Dn + h * HEADn;
    const __half* Vbase = Vp + (size_t)(b * Sn) * Dn + h * HEADn;

    auto issueK = [&](int k0, int s) {
        #pragma unroll
        for (int i = 0; i < 4; i++)
            cpasync16(&Kbb[s * HTILE + frow[i] * APH + fc8[i]],
                      &Kbase[(size_t)(k0 + frow[i]) * Dn + fc8[i]]);
    };
    auto issueV = [&](int k0, int s) {
        #pragma unroll
        for (int i = 0; i < 4; i++)
            cpasync16(&Vbb[s * HTILE + frow[i] * APH + fc8[i]],
                      &Vbase[(size_t)(k0 + frow[i]) * Dn + fc8[i]]);
    };

    #pragma unroll
    for (int i = 0; i < 4; i++)
        cpasync16(&Qs[frow[i] * APH + fc8[i]],
                  &Qp[(size_t)(b * Sn + q0 + frow[i]) * Dn + h * HEADn + fc8[i]]);
    issueK(0, 0); issueV(0, 0);
    CP_COMMIT();

    float4 accp[2][8];
    #pragma unroll
    for (int i = 0; i < 2; i++)
        #pragma unroll
        for (int j = 0; j < 8; j++) accp[i][j] = make_float4(0.f, 0.f, 0.f, 0.f);
    float lacc[4] = {0.f, 0.f, 0.f, 0.f};

    size_t abase = (size_t)bh * Sn * Sn;

    for (int kt = 0; kt <= qt; kt++) {
        int k0 = kt * 64;
        int cur = kt & 1;
        CP_WAIT0();
        __syncthreads();
        if (kt < qt) { issueK(k0 + 64, cur ^ 1); issueV(k0 + 64, cur ^ 1); CP_COMMIT(); }

        const __half* Ks = &Kbb[cur * HTILE];
        const __half* Vs = &Vbb[cur * HTILE];

        float4 accq[2][4];
        #pragma unroll
        for (int i = 0; i < 2; i++)
            #pragma unroll
            for (int j = 0; j < 4; j++) accq[i][j] = make_float4(0.f, 0.f, 0.f, 0.f);

        #pragma unroll
        for (int ko = 0; ko < 64; ko += 16) {
            unsigned a0[4], a1[4];
            ldsm_x4(a0[0], a0[1], a0[2], a0[3], &Qs[(mbase + a_r) * APH + ko + a_c]);
            ldsm_x4(a1[0], a1[1], a1[2], a1[3], &Qs[(mbase + 16 + a_r) * APH + ko + a_c]);
            #pragma unroll
            for (int ns = 0; ns < 4; ns++) {
                unsigned b0, b1;
                ldsm_x2(b0, b1, &Ks[(nbase + ns * 8 + bq_r) * APH + ko + bq_c]);
                mma_f16(accq[0][ns], a0[0], a0[1], a0[2], a0[3], b0, b1);
                mma_f16(accq[1][ns], a1[0], a1[1], a1[2], a1[3], b0, b1);
            }
        }

        unsigned ulo[2][4], uhi[2][4];
        #pragma unroll
        for (int ms = 0; ms < 2; ms++) {
            int rlo = mbase + ms * 16 + g;
            int rhi = rlo + 8;
            #pragma unroll
            for (int ns = 0; ns < 4; ns++) {
                int c0 = nbase + ns * 8 + 2 * tg;
                float sx = accq[ms][ns].x * EXSC;
                float sy = accq[ms][ns].y * EXSC;
                float sz = accq[ms][ns].z * EXSC;
                float sw = accq[ms][ns].w * EXSC;
                if (k0 + c0     > q0 + rlo) sx = -1e30f;
                if (k0 + c0 + 1 > q0 + rlo) sy = -1e30f;
                if (k0 + c0     > q0 + rhi) sz = -1e30f;
                if (k0 + c0 + 1 > q0 + rhi) sw = -1e30f;
                __half2 elo = ex2h2(__floats2half2_rn(sx, sy));
                __half2 ehi = ex2h2(__floats2half2_rn(sz, sw));
                ulo[ms][ns] = h2bits(elo);
                uhi[ms][ns] = h2bits(ehi);
                float2 flo = __half22float2(elo), fhi = __half22float2(ehi);
                lacc[ms*2+0] += flo.x + flo.y;
                lacc[ms*2+1] += fhi.x + fhi.y;
            }
        }

        #pragma unroll
        for (int j = 0; j < 2; j++) {
            #pragma unroll
            for (int dn = 0; dn < 8; dn++) {
                unsigned b0, b1;
                ldsm_x2t(b0, b1, &Vs[(nbase + j * 16 + bv_r) * APH + dn * 8]);
                mma_f16(accp[0][dn], ulo[0][2*j], uhi[0][2*j], ulo[0][2*j+1], uhi[0][2*j+1], b0, b1);
                mma_f16(accp[1][dn], ulo[1][2*j], uhi[1][2*j], ulo[1][2*j+1], uhi[1][2*j+1], b0, b1);
            }
        }
    }

    #pragma unroll
    for (int i = 0; i < 4; i++) {
        lacc[i] += __shfl_xor_sync(0xffffffffu, lacc[i], 1);
        lacc[i] += __shfl_xor_sync(0xffffffffu, lacc[i], 2);
    }
    __syncthreads();
    if (tg == 0) {
        #pragma unroll
        for (int ms = 0; ms < 2; ms++) {
            lpart[warp * 32 + ms * 16 + g]     = lacc[ms*2+0];
            lpart[warp * 32 + ms * 16 + 8 + g] = lacc[ms*2+1];
        }
    }
    if (wn == 1) {
        #pragma unroll
        for (int ms = 0; ms < 2; ms++) {
            int rl = mbase + ms * 16 + g, rh = rl + 8;
            #pragma unroll
            for (int dn = 0; dn < 8; dn++) {
                int c = dn * 8 + 2 * tg;
                *(float2*)&red[rl * 64 + c] = make_float2(accp[ms][dn].x, accp[ms][dn].y);
                *(float2*)&red[rh * 64 + c] = make_float2(accp[ms][dn].z, accp[ms][dn].w);
            }
        }
    }
    __syncthreads();
    if (t < 64) linv[t] = 1.f / (lpart[t] + lpart[t + 64]);
    __syncthreads();

    issueK(0, 0);
    CP_COMMIT();

    if (wn == 0) {
        #pragma unroll
        for (int ms = 0; ms < 2; ms++) {
            int rl = mbase + ms * 16 + g, rh = rl + 8;
            float il = linv[rl], ih = linv[rh];
            #pragma unroll
            for (int dn = 0; dn < 8; dn++) {
                int c = dn * 8 + 2 * tg;
                float2 lo = *(float2*)&red[rl * 64 + c];
                float2 hi = *(float2*)&red[rh * 64 + c];
                *(__half2*)&Oh[(size_t)(b * Sn + q0 + rl) * Dn + h * HEADn + c] =
                    __floats2half2_rn((accp[ms][dn].x + lo.x) * il, (accp[ms][dn].y + lo.y) * il);
                *(__half2*)&Oh[(size_t)(b * Sn + q0 + rh) * Dn + h * HEADn + c] =
                    __floats2half2_rn((accp[ms][dn].z + hi.x) * ih, (accp[ms][dn].w + hi.y) * ih);
            }
        }
    }

    for (int kt = 0; kt <= qt; kt++) {
        int k0 = kt * 64;
        int cur = kt & 1;
        CP_WAIT0();
        __syncthreads();
        if (kt < qt) { issueK(k0 + 64, cur ^ 1); CP_COMMIT(); }

        const __half* Ks = &Kbb[cur * HTILE];

        float4 accq[2][4];
        #pragma unroll
        for (int i = 0; i < 2; i++)
            #pragma unroll
            for (int j = 0; j < 4; j++) accq[i][j] = make_float4(0.f, 0.f, 0.f, 0.f);

        #pragma unroll
        for (int ko = 0; ko < 64; ko += 16) {
            unsigned a0[4], a1[4];
            ldsm_x4(a0[0], a0[1], a0[2], a0[3], &Qs[(mbase + a_r) * APH + ko + a_c]);
            ldsm_x4(a1[0], a1[1], a1[2], a1[3], &Qs[(mbase + 16 + a_r) * APH + ko + a_c]);
            #pragma unroll
            for (int ns = 0; ns < 4; ns++) {
                unsigned b0, b1;
                ldsm_x2(b0, b1, &Ks[(nbase + ns * 8 + bq_r) * APH + ko + bq_c]);
                mma_f16(accq[0][ns], a0[0], a0[1], a0[2], a0[3], b0, b1);
                mma_f16(accq[1][ns], a1[0], a1[1], a1[2], a1[3], b0, b1);
            }
        }

        #pragma unroll
        for (int ms = 0; ms < 2; ms++) {
            int rlo = mbase + ms * 16 + g;
            int rhi = rlo + 8;
            float ilo = linv[rlo], ihi = linv[rhi];
            #pragma unroll
            for (int ns = 0; ns < 4; ns++) {
                int c0 = nbase + ns * 8 + 2 * tg;
                float sx = accq[ms][ns].x * EXSC;
                float sy = accq[ms][ns].y * EXSC;
                float sz = accq[ms][ns].z * EXSC;
                float sw = accq[ms][ns].w * EXSC;
                if (k0 + c0     > q0 + rlo) sx = -1e30f;
                if (k0 + c0 + 1 > q0 + rlo) sy = -1e30f;
                if (k0 + c0     > q0 + rhi) sz = -1e30f;
                if (k0 + c0 + 1 > q0 + rhi) sw = -1e30f;
                float2 flo = __half22float2(ex2h2(__floats2half2_rn(sx, sy)));
                float2 fhi = __half22float2(ex2h2(__floats2half2_rn(sz, sw)));
                flo.x *= ilo; flo.y *= ilo;
                fhi.x *= ihi; fhi.y *= ihi;
                *(float2*)&attn[abase + (size_t)(q0 + rlo) * Sn + k0 + c0] = flo;
                *(float2*)&attn[abase + (size_t)(q0 + rhi) * Sn + k0 + c0] = fhi;
            }
        }
    }

    float4 z4 = make_float4(0.f, 0.f, 0.f, 0.f);
    for (int kt = qt + 1; kt < Sn / 64; kt++) {
        int k0 = kt * 64;
        #pragma unroll
        for (int i = 0; i < 8; i++) {
            int idx = t + i * 128;
            int row = idx >> 4, s4 = (idx & 15) * 4;
            *(float4*)&attn[abase + (size_t)(q0 + row) * Sn + k0 + s4] = z4;
        }
    }
}

// ---------------- launch ----------------
extern "C" void kernel_launch(void* const* d_in, const int* in_sizes, int n_in,
                              void* d_out, int out_size) {
    (void)in_sizes; (void)n_in; (void)out_size;

    const float* q  = (const float*)d_in[0];
    const float* k  = (const float*)d_in[1];
    const float* v  = (const float*)d_in[2];
    const float* Vq = (const float*)d_in[3];
    const float* Uq = (const float*)d_in[4];
    const float* bq = (const float*)d_in[5];
    const float* Vk = (const float*)d_in[6];
    const float* Uk = (const float*)d_in[7];
    const float* bk = (const float*)d_in[8];
    const float* Vv = (const float*)d_in[9];
    const float* Uv = (const float*)d_in[10];
    const float* bv = (const float*)d_in[11];
    const float* Vo = (const float*)d_in[12];
    const float* Uo = (const float*)d_in[13];
    const float* bo = (const float*)d_in[14];

    float* out  = (float*)d_out;
    float* attn = out + (size_t)Mn * Dn;

    void *p_xh, *p_tmp, *p_split, *p_q, *p_k, *p_v, *p_oh, *p_wh;
    cudaGetSymbolAddress(&p_xh, g_xh);
    cudaGetSymbolAddress(&p_tmp, g_tmp);
    cudaGetSymbolAddress(&p_split, g_split);
    cudaGetSymbolAddress(&p_q, g_qp);
    cudaGetSymbolAddress(&p_k, g_kp);
    cudaGetSymbolAddress(&p_v, g_vp);
    cudaGetSymbolAddress(&p_oh, g_oh);
    cudaGetSymbolAddress(&p_wh, g_wh);

    __half* xh   = (__half*)p_xh;
    __half* tmp0 = (__half*)p_tmp;
    __half* tmp1 = tmp0 + (size_t)Mn * RANKP;
    __half* tmp2 = tmp1 + (size_t)Mn * RANKP;
    float*  spl  = (float*)p_split;
    __half* gq = (__half*)p_q;
    __half* gk = (__half*)p_k;
    __half* gv = (__half*)p_v;
    __half* goh = (__half*)p_oh;
    __half* wh  = (__half*)p_wh;

    const size_t PSTRIDE = (size_t)Mn * RANKP;
    cudaFuncSetAttribute(attn_fused, cudaFuncAttributeMaxDynamicSharedMemorySize, ATTN_SMEM);

    // 0) merged conversions (inputs + weights)
    WPtrs wp;
    wp.src[0] = Vq; wp.src[1] = Vk; wp.src[2] = Vv;
    wp.src[3] = Uq; wp.src[4] = Uk; wp.src[5] = Uv;
    wp.src[6] = Vo; wp.src[7] = Uo;
    cvt_all<<<dim3(Mn * Dn / 4 / 256, 11), 256>>>(q, k, v, xh, wp, wh);

    // 1) down-projection q,k,v: tmp[M,224] = x @ V^T (pads zeroed)
    GemmH g1;
    g1.A[0] = xh; g1.A[1] = xh + (size_t)Mn * Dn; g1.A[2] = xh + 2 * (size_t)Mn * Dn;
    g1.B[0] = wh; g1.B[1] = wh + WSLOT; g1.B[2] = wh + 2 * (size_t)WSLOT;
    g1.bias[0] = g1.bias[1] = g1.bias[2] = nullptr;
    g1.C[0] = tmp0; g1.C[1] = tmp1; g1.C[2] = tmp2;
    gemm_h<<<dim3(4, Mn / 64, 3), 128>>>(g1, RANKn, RANKP, Dn, Dn, Dn, 0, 1, 1, 0);

    // 2) up-projection: proj = tmp @ U^T + b  (K=224, pads zero)
    GemmH g2;
    g2.A[0] = tmp0; g2.A[1] = tmp1; g2.A[2] = tmp2;
    g2.B[0] = wh + 3 * (size_t)WSLOT; g2.B[1] = wh + 4 * (size_t)WSLOT; g2.B[2] = wh + 5 * (size_t)WSLOT;
    g2.bias[0] = bq; g2.bias[1] = bk; g2.bias[2] = bv;
    g2.C[0] = gq; g2.C[1] = gk; g2.C[2] = gv;
    gemm_h<<<dim3(Dn / 64, Mn / 64, 3), 128>>>(g2, Dn, Dn, RANKP, RANKP, RANKP, 1, 1, 1, 0);

    // 3) fully fused attention
    attn_fused<<<dim3(Sn / 64, BHn), 128, ATTN_SMEM>>>(gq, gk, gv, attn, goh);

    // 4a) output down-projection, split-K=4, fp32 padded partials
    GemmH g3;
    g3.A[0] = goh; g3.B[0] = wh + 6 * (size_t)WSLOT; g3.bias[0] = nullptr; g3.C[0] = spl;
    g3.A[1] = g3.A[2] = nullptr; g3.B[1] = g3.B[2] = nullptr;
    g3.bias[1] = g3.bias[2] = nullptr; g3.C[1] = g3.C[2] = nullptr;
    gemm_h<<<dim3(4, Mn / 64, 4), 128>>>(g3, RANKn, RANKP, Dn / 4, Dn, Dn, 0, 0, 4, PSTRIDE);

    // 4b) output up-projection: sums 4 partials, K=224
    gemm_s<<<dim3(Dn / 64, Mn / 64), 128>>>(spl, PSTRIDE, wh + 7 * (size_t)WSLOT, bo, out, Dn, RANKP);
}

// round 17
// speedup vs baseline: 1.2348x; 1.2348x over previous
#include <cuda_runtime.h>
#include <cuda_fp16.h>
#include <math.h>

#define Bn    2
#define Sn    2048
#define Dn    1024
#define Hn    16
#define HEADn 64
#define RANKn 204
#define RANKP 224
#define BHn   (Bn*Hn)
#define Mn    (Bn*Sn)
#define WSLOT 262144                   // padded weight slot (256*1024 halves)

// ---------------- scratch ----------------
__device__ __half g_xh[3][(size_t)Mn*Dn];        // fp16 q,k,v inputs
__device__ __half g_tmp[3][(size_t)Mn*RANKP];    // padded down-proj
__device__ float  g_split[4][(size_t)Mn*RANKP];  // padded split-K partials
__device__ __half g_qp[(size_t)Mn*Dn];
__device__ __half g_kp[(size_t)Mn*Dn];
__device__ __half g_vp[(size_t)Mn*Dn];
__device__ __half g_oh[(size_t)Mn*Dn];
__device__ __half g_wh[8][WSLOT];                // padded fp16 weights

// ---------------- helpers ----------------
__device__ __forceinline__ void mma_f16(float4& d, unsigned a0, unsigned a1,
                                        unsigned a2, unsigned a3,
                                        unsigned b0, unsigned b1) {
    asm volatile(
        "mma.sync.aligned.m16n8k16.row.col.f32.f16.f16.f32 "
        "{%0,%1,%2,%3},{%4,%5,%6,%7},{%8,%9},{%0,%1,%2,%3};"
        : "+f"(d.x), "+f"(d.y), "+f"(d.z), "+f"(d.w)
        : "r"(a0), "r"(a1), "r"(a2), "r"(a3), "r"(b0), "r"(b1));
}

__device__ __forceinline__ void ldsm_x4(unsigned& r0, unsigned& r1, unsigned& r2,
                                        unsigned& r3, const __half* p) {
    unsigned addr = (unsigned)__cvta_generic_to_shared(p);
    asm volatile("ldmatrix.sync.aligned.m8n8.x4.shared.b16 {%0,%1,%2,%3}, [%4];"
                 : "=r"(r0), "=r"(r1), "=r"(r2), "=r"(r3) : "r"(addr));
}
__device__ __forceinline__ void ldsm_x2(unsigned& r0, unsigned& r1, const __half* p) {
    unsigned addr = (unsigned)__cvta_generic_to_shared(p);
    asm volatile("ldmatrix.sync.aligned.m8n8.x2.shared.b16 {%0,%1}, [%2];"
                 : "=r"(r0), "=r"(r1) : "r"(addr));
}
__device__ __forceinline__ void ldsm_x2t(unsigned& r0, unsigned& r1, const __half* p) {
    unsigned addr = (unsigned)__cvta_generic_to_shared(p);
    asm volatile("ldmatrix.sync.aligned.m8n8.x2.trans.shared.b16 {%0,%1}, [%2];"
                 : "=r"(r0), "=r"(r1) : "r"(addr));
}

__device__ __forceinline__ uint2 pack4(float4 v) {
    __half2 h0 = __floats2half2_rn(v.x, v.y);
    __half2 h1 = __floats2half2_rn(v.z, v.w);
    return make_uint2(reinterpret_cast<unsigned&>(h0), reinterpret_cast<unsigned&>(h1));
}

__device__ __forceinline__ __half2 ex2h2(__half2 x) {
    __half2 r;
    asm("ex2.approx.f16x2 %0, %1;"
        : "=r"(reinterpret_cast<unsigned&>(r)) : "r"(reinterpret_cast<unsigned&>(x)));
    return r;
}
__device__ __forceinline__ unsigned h2bits(__half2 x) {
    return reinterpret_cast<unsigned&>(x);
}

__device__ __forceinline__ void cpasync16(__half* dst, const __half* src) {
    unsigned d = (unsigned)__cvta_generic_to_shared(dst);
    asm volatile("cp.async.cg.shared.global [%0], [%1], 16;" :: "r"(d), "l"(src) : "memory");
}
#define CP_COMMIT() asm volatile("cp.async.commit_group;" ::: "memory")
#define CP_WAIT0()  asm volatile("cp.async.wait_group 0;"  ::: "memory")

#define EXSC 0.18033688011112042f   // 0.125 * log2(e)

// ============ weight fp32 -> padded fp16 ============
struct WPtrs { const float* src[8]; };

__global__ __launch_bounds__(256) void cvt_w(WPtrs w, __half* dst) {
    int m = blockIdx.y;
    bool isV = (m < 3) || (m == 6);
    size_t o = ((size_t)blockIdx.x * 256 + threadIdx.x) * 4;
    __half* d = dst + (size_t)m * WSLOT;
    float4 v = make_float4(0.f, 0.f, 0.f, 0.f);
    if (isV) {
        int r = (int)(o >> 10), c = (int)(o & 1023);
        if (r < RANKn) v = *(const float4*)&w.src[m][r * 1024 + c];
    } else {
        if (o >= (size_t)1024 * RANKP) return;
        int r = (int)(o / RANKP), c = (int)(o % RANKP);
        if (c < RANKn) v = *(const float4*)&w.src[m][r * RANKn + c];
    }
    *(uint2*)&d[o] = pack4(v);
}

// ============ q/k/v fp32 -> fp16 ============
__global__ __launch_bounds__(256) void cvt_x(const float* q, const float* k,
                                             const float* v, __half* dst) {
    const float* s = (blockIdx.y == 0) ? q : (blockIdx.y == 1) ? k : v;
    size_t o = ((size_t)blockIdx.x * 256 + threadIdx.x) * 4;
    float4 t = *(const float4*)&s[o];
    *(uint2*)&dst[(size_t)blockIdx.y * Mn * Dn + o] = pack4(t);
}

// ============ gemm_h: pure fp16 NT GEMM, cp.async, guard-free ============
struct GemmH {
    const __half* A[3];
    const __half* B[3];
    const float*  bias[3];
    void*         C[3];
};

#define GPH 40

__global__ __launch_bounds__(128) void gemm_h(GemmH gb, int Nreal, int Npitch,
                                              int Klen, int apitch, int bpitch,
                                              int hasBias, int outHalf,
                                              int ksplit, size_t cstride) {
    int z = blockIdx.z;
    int batch = z / ksplit, slice = z % ksplit;
    const __half* A = gb.A[batch] + slice * Klen;
    const __half* B = gb.B[batch] + slice * Klen;
    const float* bias = gb.bias[batch];
    float*  Cf = (float*)gb.C[batch] + (size_t)slice * cstride;
    __half* Ch = (__half*)gb.C[batch];

    __shared__ __half As[2][64 * GPH], Bs[2][64 * GPH];

    int t = threadIdx.x;
    int warp = t >> 5, lane = t & 31;
    int g = lane >> 2, tg = lane & 3;
    int bm = blockIdx.y * 64, bn = blockIdx.x * 64;
    int mbase = (warp & 1) * 32, nbase = (warp >> 1) * 32;

    int a_r = lane & 15, a_c = (lane >> 4) << 3;
    int b_r = lane & 7,  b_c = ((lane >> 3) & 1) << 3;

    // cp.async slots: 64 rows x 32 halves = 256 x 16B chunks, 2 per thread per matrix
    int crow[2], cc8[2];
    #pragma unroll
    for (int i = 0; i < 2; i++) { int s = t + i * 128; crow[i] = s >> 2; cc8[i] = (s & 3) * 8; }

    auto issue = [&](int k0, int st) {
        #pragma unroll
        for (int i = 0; i < 2; i++) {
            cpasync16(&As[st][crow[i] * GPH + cc8[i]],
                      &A[(size_t)(bm + crow[i]) * apitch + k0 + cc8[i]]);
            cpasync16(&Bs[st][crow[i] * GPH + cc8[i]],
                      &B[(size_t)(bn + crow[i]) * bpitch + k0 + cc8[i]]);
        }
    };

    float4 acc[2][4];
    #pragma unroll
    for (int i = 0; i < 2; i++)
        #pragma unroll
        for (int j = 0; j < 4; j++) acc[i][j] = make_float4(0.f, 0.f, 0.f, 0.f);

    int nkt = Klen / 32;
    issue(0, 0);
    CP_COMMIT();

    for (int kt = 0; kt < nkt; kt++) {
        int cur = kt & 1;
        CP_WAIT0();
        __syncthreads();
        if (kt + 1 < nkt) { issue((kt + 1) * 32, cur ^ 1); CP_COMMIT(); }

        #pragma unroll
        for (int ko = 0; ko < 32; ko += 16) {
            unsigned a0[4], a1[4];
            ldsm_x4(a0[0], a0[1], a0[2], a0[3], &As[cur][(mbase + a_r) * GPH + ko + a_c]);
            ldsm_x4(a1[0], a1[1], a1[2], a1[3], &As[cur][(mbase + 16 + a_r) * GPH + ko + a_c]);
            #pragma unroll
            for (int ns = 0; ns < 4; ns++) {
                unsigned b0, b1;
                ldsm_x2(b0, b1, &Bs[cur][(nbase + ns * 8 + b_r) * GPH + ko + b_c]);
                mma_f16(acc[0][ns], a0[0], a0[1], a0[2], a0[3], b0, b1);
                mma_f16(acc[1][ns], a1[0], a1[1], a1[2], a1[3], b0, b1);
            }
        }
    }

    #pragma unroll
    for (int ms = 0; ms < 2; ms++) {
        #pragma unroll
        for (int ns = 0; ns < 4; ns++) {
            int col = bn + nbase + ns * 8 + 2 * tg;
            if (col < Npitch) {
                bool real = (col < Nreal);
                float b0 = (hasBias && real) ? bias[col]     : 0.f;
                float b1 = (hasBias && real) ? bias[col + 1] : 0.f;
                int r0 = bm + mbase + ms * 16 + g;
                float vx = real ? acc[ms][ns].x + b0 : 0.f;
                float vy = real ? acc[ms][ns].y + b1 : 0.f;
                float vz = real ? acc[ms][ns].z + b0 : 0.f;
                float vw = real ? acc[ms][ns].w + b1 : 0.f;
                if (outHalf) {
                    *(__half2*)&Ch[(size_t)r0 * Npitch + col]       = __floats2half2_rn(vx, vy);
                    *(__half2*)&Ch[(size_t)(r0 + 8) * Npitch + col] = __floats2half2_rn(vz, vw);
                } else {
                    *(float2*)&Cf[(size_t)r0 * Npitch + col]       = make_float2(vx, vy);
                    *(float2*)&Cf[(size_t)(r0 + 8) * Npitch + col] = make_float2(vz, vw);
                }
            }
        }
    }
}

// ============ gemm_s: sums 4 fp32 partial A buffers, fp16 B, fp32 out ============
__global__ __launch_bounds__(128) void gemm_s(const float* __restrict__ A, size_t astride,
                                              const __half* __restrict__ Bp,
                                              const float* __restrict__ bias,
                                              float* __restrict__ C, int N, int K) {
    __shared__ __half As[2][64 * GPH], Bs[2][64 * GPH];

    int t = threadIdx.x;
    int warp = t >> 5, lane = t & 31;
    int g = lane >> 2, tg = lane & 3;
    int bm = blockIdx.y * 64, bn = blockIdx.x * 64;
    int mbase = (warp & 1) * 32, nbase = (warp >> 1) * 32;

    int a_r = lane & 15, a_c = (lane >> 4) << 3;
    int b_r = lane & 7,  b_c = ((lane >> 3) & 1) << 3;

    int lrow[4], lsc[4];
    #pragma unroll
    for (int i = 0; i < 4; i++) { int idx = t + i * 128; lrow[i] = idx >> 3; lsc[i] = idx & 7; }

    float4 ra[4];
    uint2  rbh[4];
    auto fetch = [&](int k0) {
        #pragma unroll
        for (int i = 0; i < 4; i++) {
            int kk = k0 + lsc[i] * 4;
            size_t aoff = (size_t)(bm + lrow[i]) * K + kk;
            ra[i] = make_float4(0.f, 0.f, 0.f, 0.f);
            #pragma unroll
            for (int p = 0; p < 4; p++) {
                float4 v = *(const float4*)&A[p * astride + aoff];
                ra[i].x += v.x; ra[i].y += v.y; ra[i].z += v.z; ra[i].w += v.w;
            }
            rbh[i] = *(const uint2*)&Bp[(size_t)(bn + lrow[i]) * K + kk];
        }
    };
    auto stage = [&](int s) {
        #pragma unroll
        for (int i = 0; i < 4; i++) {
            *(uint2*)&As[s][lrow[i] * GPH + lsc[i] * 4] = pack4(ra[i]);
            *(uint2*)&Bs[s][lrow[i] * GPH + lsc[i] * 4] = rbh[i];
        }
    };

    float4 acc[2][4];
    #pragma unroll
    for (int i = 0; i < 2; i++)
        #pragma unroll
        for (int j = 0; j < 4; j++) acc[i][j] = make_float4(0.f, 0.f, 0.f, 0.f);

    int nkt = K / 32;
    fetch(0);
    stage(0);
    __syncthreads();

    for (int kt = 0; kt < nkt; kt++) {
        int cur = kt & 1;
        if (kt + 1 < nkt) fetch((kt + 1) * 32);

        #pragma unroll
        for (int ko = 0; ko < 32; ko += 16) {
            unsigned a0[4], a1[4];
            ldsm_x4(a0[0], a0[1], a0[2], a0[3], &As[cur][(mbase + a_r) * GPH + ko + a_c]);
            ldsm_x4(a1[0], a1[1], a1[2], a1[3], &As[cur][(mbase + 16 + a_r) * GPH + ko + a_c]);
            #pragma unroll
            for (int ns = 0; ns < 4; ns++) {
                unsigned b0, b1;
                ldsm_x2(b0, b1, &Bs[cur][(nbase + ns * 8 + b_r) * GPH + ko + b_c]);
                mma_f16(acc[0][ns], a0[0], a0[1], a0[2], a0[3], b0, b1);
                mma_f16(acc[1][ns], a1[0], a1[1], a1[2], a1[3], b0, b1);
            }
        }

        if (kt + 1 < nkt) {
            stage(cur ^ 1);
            __syncthreads();
        }
    }

    #pragma unroll
    for (int ms = 0; ms < 2; ms++) {
        #pragma unroll
        for (int ns = 0; ns < 4; ns++) {
            int col = bn + nbase + ns * 8 + 2 * tg;
            float b0 = bias[col], b1 = bias[col + 1];
            int r0 = bm + mbase + ms * 16 + g;
            *(float2*)&C[(size_t)r0 * N + col]       = make_float2(acc[ms][ns].x + b0, acc[ms][ns].y + b1);
            *(float2*)&C[(size_t)(r0 + 8) * N + col] = make_float2(acc[ms][ns].z + b0, acc[ms][ns].w + b1);
        }
    }
}

// ============ fused causal attention (round-14, unchanged) ============
#define APH 72
#define HTILE (64*APH)
#define HOFF_K HTILE
#define HOFF_V (3*HTILE)
#define SM_H   (5*HTILE)
#define OFF_LP (SM_H*2)
#define OFF_LI (OFF_LP + 512)
#define ATTN_SMEM (OFF_LI + 256)

__global__ __launch_bounds__(128, 4) void attn_fused(const __half* __restrict__ Qp,
                                                     const __half* __restrict__ Kp,
                                                     const __half* __restrict__ Vp,
                                                     float* __restrict__ attn,
                                                     __half* __restrict__ Oh) {
    extern __shared__ char smraw[];
    __half* Qs = (__half*)smraw;
    __half* Kbb = (__half*)smraw + HOFF_K;
    __half* Vbb = (__half*)smraw + HOFF_V;
    float* red   = (float*)(smraw + 3 * HTILE * 2);
    float* lpart = (float*)(smraw + OFF_LP);
    float* linv  = (float*)(smraw + OFF_LI);

    int qt = gridDim.x - 1 - blockIdx.x;
    int bh = blockIdx.y;
    int b = bh >> 4, h = bh & 15;
    int q0 = qt * 64;

    int t = threadIdx.x;
    int warp = t >> 5, lane = t & 31;
    int g = lane >> 2, tg = lane & 3;
    int wm = warp & 1, wn = warp >> 1;
    int mbase = wm * 32, nbase = wn * 32;

    int a_r = lane & 15, a_c = (lane >> 4) << 3;
    int bq_r = lane & 7, bq_c = ((lane >> 3) & 1) << 3;
    int bv_r = lane & 15;

    int frow[4], fc8[4];
    #pragma unroll
    for (int i = 0; i < 4; i++) { int s = t + i * 128; frow[i] = s >> 3; fc8[i] = (s & 7) * 8; }

    const __half* Kbase = Kp + (size_t)(b * Sn) * Dn + h * HEADn;
    const __half* Vbase = Vp + (size_t)(b * Sn) * Dn + h * HEADn;

    auto issueK = [&](int k0, int s) {
        #pragma unroll
        for (int i = 0; i < 4; i++)
            cpasync16(&Kbb[s * HTILE + frow[i] * APH + fc8[i]],
                      &Kbase[(size_t)(k0 + frow[i]) * Dn + fc8[i]]);
    };
    auto issueV = [&](int k0, int s) {
        #pragma unroll
        for (int i = 0; i < 4; i++)
            cpasync16(&Vbb[s * HTILE + frow[i] * APH + fc8[i]],
                      &Vbase[(size_t)(k0 + frow[i]) * Dn + fc8[i]]);
    };

    #pragma unroll
    for (int i = 0; i < 4; i++)
        cpasync16(&Qs[frow[i] * APH + fc8[i]],
                  &Qp[(size_t)(b * Sn + q0 + frow[i]) * Dn + h * HEADn + fc8[i]]);
    issueK(0, 0); issueV(0, 0);
    CP_COMMIT();

    float4 accp[2][8];
    #pragma unroll
    for (int i = 0; i < 2; i++)
        #pragma unroll
        for (int j = 0; j < 8; j++) accp[i][j] = make_float4(0.f, 0.f, 0.f, 0.f);
    float lacc[4] = {0.f, 0.f, 0.f, 0.f};

    size_t abase = (size_t)bh * Sn * Sn;

    for (int kt = 0; kt <= qt; kt++) {
        int k0 = kt * 64;
        int cur = kt & 1;
        CP_WAIT0();
        __syncthreads();
        if (kt < qt) { issueK(k0 + 64, cur ^ 1); issueV(k0 + 64, cur ^ 1); CP_COMMIT(); }

        const __half* Ks = &Kbb[cur * HTILE];
        const __half* Vs = &Vbb[cur * HTILE];

        float4 accq[2][4];
        #pragma unroll
        for (int i = 0; i < 2; i++)
            #pragma unroll
            for (int j = 0; j < 4; j++) accq[i][j] = make_float4(0.f, 0.f, 0.f, 0.f);

        #pragma unroll
        for (int ko = 0; ko < 64; ko += 16) {
            unsigned a0[4], a1[4];
            ldsm_x4(a0[0], a0[1], a0[2], a0[3], &Qs[(mbase + a_r) * APH + ko + a_c]);
            ldsm_x4(a1[0], a1[1], a1[2], a1[3], &Qs[(mbase + 16 + a_r) * APH + ko + a_c]);
            #pragma unroll
            for (int ns = 0; ns < 4; ns++) {
                unsigned b0, b1;
                ldsm_x2(b0, b1, &Ks[(nbase + ns * 8 + bq_r) * APH + ko + bq_c]);
                mma_f16(accq[0][ns], a0[0], a0[1], a0[2], a0[3], b0, b1);
                mma_f16(accq[1][ns], a1[0], a1[1], a1[2], a1[3], b0, b1);
            }
        }

        unsigned ulo[2][4], uhi[2][4];
        #pragma unroll
        for (int ms = 0; ms < 2; ms++) {
            int rlo = mbase + ms * 16 + g;
            int rhi = rlo + 8;
            #pragma unroll
            for (int ns = 0; ns < 4; ns++) {
                int c0 = nbase + ns * 8 + 2 * tg;
                float sx = accq[ms][ns].x * EXSC;
                float sy = accq[ms][ns].y * EXSC;
                float sz = accq[ms][ns].z * EXSC;
                float sw = accq[ms][ns].w * EXSC;
                if (k0 + c0     > q0 + rlo) sx = -1e30f;
                if (k0 + c0 + 1 > q0 + rlo) sy = -1e30f;
                if (k0 + c0     > q0 + rhi) sz = -1e30f;
                if (k0 + c0 + 1 > q0 + rhi) sw = -1e30f;
                __half2 elo = ex2h2(__floats2half2_rn(sx, sy));
                __half2 ehi = ex2h2(__floats2half2_rn(sz, sw));
                ulo[ms][ns] = h2bits(elo);
                uhi[ms][ns] = h2bits(ehi);
                float2 flo = __half22float2(elo), fhi = __half22float2(ehi);
                lacc[ms*2+0] += flo.x + flo.y;
                lacc[ms*2+1] += fhi.x + fhi.y;
            }
        }

        #pragma unroll
        for (int j = 0; j < 2; j++) {
            #pragma unroll
            for (int dn = 0; dn < 8; dn++) {
                unsigned b0, b1;
                ldsm_x2t(b0, b1, &Vs[(nbase + j * 16 + bv_r) * APH + dn * 8]);
                mma_f16(accp[0][dn], ulo[0][2*j], uhi[0][2*j], ulo[0][2*j+1], uhi[0][2*j+1], b0, b1);
                mma_f16(accp[1][dn], ulo[1][2*j], uhi[1][2*j], ulo[1][2*j+1], uhi[1][2*j+1], b0, b1);
            }
        }
    }

    #pragma unroll
    for (int i = 0; i < 4; i++) {
        lacc[i] += __shfl_xor_sync(0xffffffffu, lacc[i], 1);
        lacc[i] += __shfl_xor_sync(0xffffffffu, lacc[i], 2);
    }
    __syncthreads();
    if (tg == 0) {
        #pragma unroll
        for (int ms = 0; ms < 2; ms++) {
            lpart[warp * 32 + ms * 16 + g]     = lacc[ms*2+0];
            lpart[warp * 32 + ms * 16 + 8 + g] = lacc[ms*2+1];
        }
    }
    if (wn == 1) {
        #pragma unroll
        for (int ms = 0; ms < 2; ms++) {
            int rl = mbase + ms * 16 + g, rh = rl + 8;
            #pragma unroll
            for (int dn = 0; dn < 8; dn++) {
                int c = dn * 8 + 2 * tg;
                *(float2*)&red[rl * 64 + c] = make_float2(accp[ms][dn].x, accp[ms][dn].y);
                *(float2*)&red[rh * 64 + c] = make_float2(accp[ms][dn].z, accp[ms][dn].w);
            }
        }
    }
    __syncthreads();
    if (t < 64) linv[t] = 1.f / (lpart[t] + lpart[t + 64]);
    __syncthreads();

    issueK(0, 0);
    CP_COMMIT();

    if (wn == 0) {
        #pragma unroll
        for (int ms = 0; ms < 2; ms++) {
            int rl = mbase + ms * 16 + g, rh = rl + 8;
            float il = linv[rl], ih = linv[rh];
            #pragma unroll
            for (int dn = 0; dn < 8; dn++) {
                int c = dn * 8 + 2 * tg;
                float2 lo = *(float2*)&red[rl * 64 + c];
                float2 hi = *(float2*)&red[rh * 64 + c];
                *(__half2*)&Oh[(size_t)(b * Sn + q0 + rl) * Dn + h * HEADn + c] =
                    __floats2half2_rn((accp[ms][dn].x + lo.x) * il, (accp[ms][dn].y + lo.y) * il);
                *(__half2*)&Oh[(size_t)(b * Sn + q0 + rh) * Dn + h * HEADn + c] =
                    __floats2half2_rn((accp[ms][dn].z + hi.x) * ih, (accp[ms][dn].w + hi.y) * ih);
            }
        }
    }

    for (int kt = 0; kt <= qt; kt++) {
        int k0 = kt * 64;
        int cur = kt & 1;
        CP_WAIT0();
        __syncthreads();
        if (kt < qt) { issueK(k0 + 64, cur ^ 1); CP_COMMIT(); }

        const __half* Ks = &Kbb[cur * HTILE];

        float4 accq[2][4];
        #pragma unroll
        for (int i = 0; i < 2; i++)
            #pragma unroll
            for (int j = 0; j < 4; j++) accq[i][j] = make_float4(0.f, 0.f, 0.f, 0.f);

        #pragma unroll
        for (int ko = 0; ko < 64; ko += 16) {
            unsigned a0[4], a1[4];
            ldsm_x4(a0[0], a0[1], a0[2], a0[3], &Qs[(mbase + a_r) * APH + ko + a_c]);
            ldsm_x4(a1[0], a1[1], a1[2], a1[3], &Qs[(mbase + 16 + a_r) * APH + ko + a_c]);
            #pragma unroll
            for (int ns = 0; ns < 4; ns++) {
                unsigned b0, b1;
                ldsm_x2(b0, b1, &Ks[(nbase + ns * 8 + bq_r) * APH + ko + bq_c]);
                mma_f16(accq[0][ns], a0[0], a0[1], a0[2], a0[3], b0, b1);
                mma_f16(accq[1][ns], a1[0], a1[1], a1[2], a1[3], b0, b1);
            }
        }

        #pragma unroll
        for (int ms = 0; ms < 2; ms++) {
            int rlo = mbase + ms * 16 + g;
            int rhi = rlo + 8;
            float ilo = linv[rlo], ihi = linv[rhi];
            #pragma unroll
            for (int ns = 0; ns < 4; ns++) {
                int c0 = nbase + ns * 8 + 2 * tg;
                float sx = accq[ms][ns].x * EXSC;
                float sy = accq[ms][ns].y * EXSC;
                float sz = accq[ms][ns].z * EXSC;
                float sw = accq[ms][ns].w * EXSC;
                if (k0 + c0     > q0 + rlo) sx = -1e30f;
                if (k0 + c0 + 1 > q0 + rlo) sy = -1e30f;
                if (k0 + c0     > q0 + rhi) sz = -1e30f;
                if (k0 + c0 + 1 > q0 + rhi) sw = -1e30f;
                float2 flo = __half22float2(ex2h2(__floats2half2_rn(sx, sy)));
                float2 fhi = __half22float2(ex2h2(__floats2half2_rn(sz, sw)));
                flo.x *= ilo; flo.y *= ilo;
                fhi.x *= ihi; fhi.y *= ihi;
                *(float2*)&attn[abase + (size_t)(q0 + rlo) * Sn + k0 + c0] = flo;
                *(float2*)&attn[abase + (size_t)(q0 + rhi) * Sn + k0 + c0] = fhi;
            }
        }
    }

    float4 z4 = make_float4(0.f, 0.f, 0.f, 0.f);
    for (int kt = qt + 1; kt < Sn / 64; kt++) {
        int k0 = kt * 64;
        #pragma unroll
        for (int i = 0; i < 8; i++) {
            int idx = t + i * 128;
            int row = idx >> 4, s4 = (idx & 15) * 4;
            *(float4*)&attn[abase + (size_t)(q0 + row) * Sn + k0 + s4] = z4;
        }
    }
}

// ---------------- launch ----------------
extern "C" void kernel_launch(void* const* d_in, const int* in_sizes, int n_in,
                              void* d_out, int out_size) {
    (void)in_sizes; (void)n_in; (void)out_size;

    const float* q  = (const float*)d_in[0];
    const float* k  = (const float*)d_in[1];
    const float* v  = (const float*)d_in[2];
    const float* Vq = (const float*)d_in[3];
    const float* Uq = (const float*)d_in[4];
    const float* bq = (const float*)d_in[5];
    const float* Vk = (const float*)d_in[6];
    const float* Uk = (const float*)d_in[7];
    const float* bk = (const float*)d_in[8];
    const float* Vv = (const float*)d_in[9];
    const float* Uv = (const float*)d_in[10];
    const float* bv = (const float*)d_in[11];
    const float* Vo = (const float*)d_in[12];
    const float* Uo = (const float*)d_in[13];
    const float* bo = (const float*)d_in[14];

    float* out  = (float*)d_out;
    float* attn = out + (size_t)Mn * Dn;

    void *p_xh, *p_tmp, *p_split, *p_q, *p_k, *p_v, *p_oh, *p_wh;
    cudaGetSymbolAddress(&p_xh, g_xh);
    cudaGetSymbolAddress(&p_tmp, g_tmp);
    cudaGetSymbolAddress(&p_split, g_split);
    cudaGetSymbolAddress(&p_q, g_qp);
    cudaGetSymbolAddress(&p_k, g_kp);
    cudaGetSymbolAddress(&p_v, g_vp);
    cudaGetSymbolAddress(&p_oh, g_oh);
    cudaGetSymbolAddress(&p_wh, g_wh);

    __half* xh   = (__half*)p_xh;
    __half* tmp0 = (__half*)p_tmp;
    __half* tmp1 = tmp0 + (size_t)Mn * RANKP;
    __half* tmp2 = tmp1 + (size_t)Mn * RANKP;
    float*  spl  = (float*)p_split;
    __half* gq = (__half*)p_q;
    __half* gk = (__half*)p_k;
    __half* gv = (__half*)p_v;
    __half* goh = (__half*)p_oh;
    __half* wh  = (__half*)p_wh;

    const size_t PSTRIDE = (size_t)Mn * RANKP;
    cudaFuncSetAttribute(attn_fused, cudaFuncAttributeMaxDynamicSharedMemorySize, ATTN_SMEM);

    // 0) convert weights + inputs to fp16 (padded)
    WPtrs wp;
    wp.src[0] = Vq; wp.src[1] = Vk; wp.src[2] = Vv;
    wp.src[3] = Uq; wp.src[4] = Uk; wp.src[5] = Uv;
    wp.src[6] = Vo; wp.src[7] = Uo;
    cvt_w<<<dim3(WSLOT / 4 / 256, 8), 256>>>(wp, wh);
    cvt_x<<<dim3(Mn * Dn / 4 / 256, 3), 256>>>(q, k, v, xh);

    // 1) down-projection q,k,v: tmp[M,224] = x @ V^T (pads zeroed)
    GemmH g1;
    g1.A[0] = xh; g1.A[1] = xh + (size_t)Mn * Dn; g1.A[2] = xh + 2 * (size_t)Mn * Dn;
    g1.B[0] = wh; g1.B[1] = wh + WSLOT; g1.B[2] = wh + 2 * (size_t)WSLOT;
    g1.bias[0] = g1.bias[1] = g1.bias[2] = nullptr;
    g1.C[0] = tmp0; g1.C[1] = tmp1; g1.C[2] = tmp2;
    gemm_h<<<dim3(4, Mn / 64, 3), 128>>>(g1, RANKn, RANKP, Dn, Dn, Dn, 0, 1, 1, 0);

    // 2) up-projection: proj = tmp @ U^T + b  (K=224, pads contribute zero)
    GemmH g2;
    g2.A[0] = tmp0; g2.A[1] = tmp1; g2.A[2] = tmp2;
    g2.B[0] = wh + 3 * (size_t)WSLOT; g2.B[1] = wh + 4 * (size_t)WSLOT; g2.B[2] = wh + 5 * (size_t)WSLOT;
    g2.bias[0] = bq; g2.bias[1] = bk; g2.bias[2] = bv;
    g2.C[0] = gq; g2.C[1] = gk; g2.C[2] = gv;
    gemm_h<<<dim3(Dn / 64, Mn / 64, 3), 128>>>(g2, Dn, Dn, RANKP, RANKP, RANKP, 1, 1, 1, 0);

    // 3) fully fused attention (round-14)
    attn_fused<<<dim3(Sn / 64, BHn), 128, ATTN_SMEM>>>(gq, gk, gv, attn, goh);

    // 4a) output down-projection, split-K=4, fp32 padded partials
    GemmH g3;
    g3.A[0] = goh; g3.B[0] = wh + 6 * (size_t)WSLOT; g3.bias[0] = nullptr; g3.C[0] = spl;
    g3.A[1] = g3.A[2] = nullptr; g3.B[1] = g3.B[2] = nullptr;
    g3.bias[1] = g3.bias[2] = nullptr; g3.C[1] = g3.C[2] = nullptr;
    gemm_h<<<dim3(4, Mn / 64, 4), 128>>>(g3, RANKn, RANKP, Dn / 4, Dn, Dn, 0, 0, 4, PSTRIDE);

    // 4b) output up-projection: sums 4 partials, K=224 (pads zero)
    gemm_s<<<dim3(Dn / 64, Mn / 64), 128>>>(spl, PSTRIDE, wh + 7 * (size_t)WSLOT, bo, out, Dn, RANKP);
}